// round 5
// baseline (speedup 1.0000x reference)
#include <cuda_runtime.h>

#define H 512
#define W 512
#define HW (H * W)
#define BN_EPS 1e-5f

typedef unsigned long long u64;

// Precomputed effective weights (written by prep part of kernel 1).
__device__ float g_Weff[675];   // [(c*5+u)*5+v]*9+k : scaled 5x5 weights on input
__device__ float g_W0[243];     // [(j*3+u)*3+v]*9+k : scaled 3x3 weights on input0
__device__ float g_Shift[9];    // BN shift per k

// ---------------- packed f32x2 helpers ----------------
__device__ __forceinline__ u64 pk(float a, float b) {
    u64 d;
    asm("mov.b64 %0, {%1, %2};" : "=l"(d) : "f"(a), "f"(b));
    return d;
}
__device__ __forceinline__ void upk(u64 d, float& a, float& b) {
    asm("mov.b64 {%0, %1}, %2;" : "=f"(a), "=f"(b) : "l"(d));
}
__device__ __forceinline__ void fma2(u64& c, u64 a, u64 b) {
    asm("fma.rn.f32x2 %0, %1, %2, %0;" : "+l"(c) : "l"(a), "l"(b));
}
__device__ __forceinline__ u64 add2(u64 a, u64 b) {
    u64 d;
    asm("add.rn.f32x2 %0, %1, %2;" : "=l"(d) : "l"(a), "l"(b));
    return d;
}

// ---------------------------------------------------------------------------
// Kernel 1: last block = prep (fold conv+BN into effective weights);
//           other blocks = exact border ring (double zero-pad semantics).
// The two parts are independent (border reads raw cw; main reads g_*).
// ---------------------------------------------------------------------------
__global__ void prep_border_kernel(const float* __restrict__ ker,
                                   const float* __restrict__ in,
                                   const float* __restrict__ in0,
                                   const float* __restrict__ cw,
                                   const float* __restrict__ gam,
                                   const float* __restrict__ bet,
                                   const float* __restrict__ mu,
                                   const float* __restrict__ var,
                                   float* __restrict__ out, int total) {
    if (blockIdx.x == gridDim.x - 1) {
        // ---- prep part ----
        for (int tid = threadIdx.x; tid < 927; tid += blockDim.x) {
            if (tid < 675) {
                int k = tid % 9;
                int rest = tid / 9;
                int v = rest % 5; rest /= 5;
                int u = rest % 5;
                int c = rest / 5;
                float s = gam[k] * rsqrtf(var[k] + BN_EPS);
                float sum = 0.f;
                for (int ti = 0; ti < 3; ti++) {
                    int di = u - ti;
                    if (di < 0 || di > 2) continue;
                    for (int tj = 0; tj < 3; tj++) {
                        int dj = v - tj;
                        if (dj < 0 || dj > 2) continue;
                        int t = ti * 3 + tj;
                        if (c == 0 && t >= 4 && t <= 6) continue;  // replaced rows
                        sum += cw[((k * 27 + c * 9 + t) * 3 + di) * 3 + dj];
                    }
                }
                g_Weff[tid] = s * sum;
            } else if (tid < 675 + 243) {
                int i = tid - 675;
                int k = i % 9;
                int rest = i / 9;
                int v = rest % 3; rest /= 3;
                int u = rest % 3;
                int j = rest / 3;
                float s = gam[k] * rsqrtf(var[k] + BN_EPS);
                g_W0[i] = s * cw[((k * 27 + 4 + j) * 3 + u) * 3 + v];
            } else {
                int k = tid - 918;
                float s = gam[k] * rsqrtf(var[k] + BN_EPS);
                g_Shift[k] = bet[k] - mu[k] * s;
            }
        }
        return;
    }

    // ---- border part ----
    __shared__ float sw[2187];
    for (int i = threadIdx.x; i < 2187; i += blockDim.x) sw[i] = cw[i];
    __syncthreads();

    int gid = blockIdx.x * blockDim.x + threadIdx.x;
    if (gid >= total) return;

    const int RING = 4 * W - 4;  // 2044
    int b = gid / RING, pos = gid % RING;
    int h, w;
    if (pos < W)            { h = 0;       w = pos; }
    else if (pos < 2 * W)   { h = H - 1;   w = pos - W; }
    else {
        int p2 = pos - 2 * W;
        h = 1 + (p2 >> 1);
        w = (p2 & 1) ? (W - 1) : 0;
    }

    float acc[9];
#pragma unroll
    for (int k = 0; k < 9; k++) acc[k] = 0.f;

    const float* inb  = in  + (size_t)b * 3 * HW;
    const float* in0b = in0 + (size_t)b * 3 * HW;

#pragma unroll 1
    for (int dy = -1; dy <= 1; dy++) {
#pragma unroll 1
        for (int dx = -1; dx <= 1; dx++) {
            int qy = h + dy, qx = w + dx;
            if (qy < 0 || qy >= H || qx < 0 || qx >= W) continue;  // x zero-pad
            int didx = (dy + 1) * 3 + (dx + 1);
#pragma unroll 1
            for (int ch = 0; ch < 27; ch++) {
                float val;
                if (ch >= 4 && ch <= 6) {
                    val = in0b[(ch - 4) * HW + qy * W + qx];
                } else {
                    int c = ch / 9, t = ch % 9;
                    int py = qy + t / 3 - 1, px = qx + t % 3 - 1;
                    val = (py >= 0 && py < H && px >= 0 && px < W)
                              ? inb[c * HW + py * W + px] : 0.f;
                }
#pragma unroll
                for (int k = 0; k < 9; k++)
                    acc[k] = fmaf(sw[(k * 27 + ch) * 9 + didx], val, acc[k]);
            }
        }
    }

    float r = 0.f;
#pragma unroll
    for (int k = 0; k < 9; k++) {
        float s  = gam[k] * rsqrtf(var[k] + BN_EPS);
        float sh = bet[k] - mu[k] * s;
        r = fmaf(ker[((size_t)b * 9 + k) * HW + h * W + w], fmaf(s, acc[k], sh), r);
    }
    out[(size_t)b * HW + h * W + w] = r;
}

// ---------------------------------------------------------------------------
// Row loaders: packed pairs e[i]={v2i,v2i+1}, o[i]={v2i+1,v2i+2} over the
// 8-wide window [w0-2, w0+5].
// ---------------------------------------------------------------------------
__device__ __forceinline__ void load_row8_fast(const float* __restrict__ p,
                                               u64 e[4], u64 o[3]) {
    // p = row + w0; w0 is a multiple of 4 -> 8B alignment for p-2.
    e[0] = *(const u64*)(p - 2);
    e[1] = *(const u64*)(p);
    e[2] = *(const u64*)(p + 2);
    e[3] = *(const u64*)(p + 4);
    float v0, v1, v2, v3, v4, v5, v6, v7;
    upk(e[0], v0, v1); upk(e[1], v2, v3); upk(e[2], v4, v5); upk(e[3], v6, v7);
    o[0] = pk(v1, v2); o[1] = pk(v3, v4); o[2] = pk(v5, v6);
}

__device__ __forceinline__ void load_row8_guard(const float* __restrict__ rowp, int w0,
                                                bool rowok, bool colsafe,
                                                u64 e[4], u64 o[3]) {
    float v[8];
    if (rowok && colsafe) {
#pragma unroll
        for (int i = 0; i < 4; i++)
            e[i] = *(const u64*)(rowp + w0 - 2 + 2 * i);
#pragma unroll
        for (int i = 0; i < 4; i++) upk(e[i], v[2 * i], v[2 * i + 1]);
    } else if (rowok) {
#pragma unroll
        for (int i = 0; i < 8; i++) {
            int ww = w0 - 2 + i;
            v[i] = (ww >= 0 && ww < W) ? rowp[ww] : 0.f;
        }
#pragma unroll
        for (int i = 0; i < 4; i++) e[i] = pk(v[2 * i], v[2 * i + 1]);
    } else {
#pragma unroll
        for (int i = 0; i < 8; i++) v[i] = 0.f;
#pragma unroll
        for (int i = 0; i < 4; i++) e[i] = 0ull;
    }
#pragma unroll
    for (int i = 0; i < 3; i++) o[i] = pk(v[2 * i + 1], v[2 * i + 2]);
}

// Apply 9 packed weights for one tap v to both pixel pairs.
__device__ __forceinline__ void apply9(const float2* __restrict__ wp,
                                       u64 d0, u64 d1, u64 acc0[9], u64 acc1[9]) {
#pragma unroll
    for (int k = 0; k < 9; k++) {
        u64 w2 = *(const u64*)&wp[k];   // LDS.64 broadcast
        fma2(acc0[k], w2, d0);
        fma2(acc1[k], w2, d1);
    }
}

// ---------------------------------------------------------------------------
// Kernel 2: main fused kernel. Block = 8x16 threads, thread -> 4 px along w.
// Fast path (interior blocks): branch-free, fully unrolled, high MLP.
// ---------------------------------------------------------------------------
__global__ __launch_bounds__(128, 4) void cspn_main(const float* __restrict__ ker,
                                                    const float* __restrict__ in,
                                                    const float* __restrict__ in0,
                                                    float* __restrict__ out) {
    __shared__ float2 sW[675];   // duplicated {w,w}
    __shared__ float2 s0[243];
    __shared__ u64 sS[9];

    int tid = threadIdx.y * 8 + threadIdx.x;
    for (int i = tid; i < 675; i += 128) { float wv = g_Weff[i]; sW[i] = make_float2(wv, wv); }
    for (int i = tid; i < 243; i += 128) { float wv = g_W0[i];   s0[i] = make_float2(wv, wv); }
    if (tid < 9) { float sh = g_Shift[tid]; sS[tid] = pk(sh, sh); }
    __syncthreads();

    const int b  = blockIdx.z;
    const int h  = blockIdx.y * 16 + threadIdx.y;
    const int w0 = blockIdx.x * 32 + threadIdx.x * 4;

    u64 acc0[9], acc1[9];
#pragma unroll
    for (int k = 0; k < 9; k++) { acc0[k] = 0ull; acc1[k] = 0ull; }

    const float* inb  = in  + (size_t)b * 3 * HW;
    const float* in0b = in0 + (size_t)b * 3 * HW;

    const bool fast = (blockIdx.x >= 1) && (blockIdx.x <= (W / 32) - 2) &&
                      (blockIdx.y >= 1) && (blockIdx.y <= (H / 16) - 2);

    if (fast) {
        // ---- branch-free fully-unrolled path ----
        const float* base5 = inb + (h - 2) * W + w0;     // + c*HW + u*W
#pragma unroll
        for (int c = 0; c < 3; c++) {
#pragma unroll
            for (int u = 0; u < 5; u++) {
                u64 e[4], o[3];
                load_row8_fast(base5 + c * HW + u * W, e, o);
                const float2* wrow = &sW[(c * 5 + u) * 45];
                apply9(wrow +  0, e[0], e[1], acc0, acc1);   // v=0: idx 0,2
                apply9(wrow +  9, o[0], o[1], acc0, acc1);   // v=1: idx 1,3
                apply9(wrow + 18, e[1], e[2], acc0, acc1);   // v=2: idx 2,4
                apply9(wrow + 27, o[1], o[2], acc0, acc1);   // v=3: idx 3,5
                apply9(wrow + 36, e[2], e[3], acc0, acc1);   // v=4: idx 4,6
            }
        }
        const float* base3 = in0b + (h - 1) * W + w0;
#pragma unroll
        for (int j3 = 0; j3 < 3; j3++) {
#pragma unroll
            for (int u = 0; u < 3; u++) {
                u64 e[4], o[3];
                load_row8_fast(base3 + j3 * HW + u * W, e, o);
                const float2* wrow = &s0[(j3 * 3 + u) * 27];
                apply9(wrow +  0, o[0], o[1], acc0, acc1);   // v=0: idx 1,3
                apply9(wrow +  9, e[1], e[2], acc0, acc1);   // v=1: idx 2,4
                apply9(wrow + 18, o[1], o[2], acc0, acc1);   // v=2: idx 3,5
            }
        }
    } else {
        // ---- guarded path (edge blocks) ----
        const bool colsafe = (w0 >= 2) && (w0 + 6 <= W);
#pragma unroll 1
        for (int c = 0; c < 3; c++) {
            const float* inc = inb + c * HW;
#pragma unroll 1
            for (int u = 0; u < 5; u++) {
                int r = h + u - 2;
                u64 e[4], o[3];
                load_row8_guard(inc + r * W, w0, (r >= 0 && r < H), colsafe, e, o);
                const float2* wrow = &sW[(c * 5 + u) * 45];
                apply9(wrow +  0, e[0], e[1], acc0, acc1);
                apply9(wrow +  9, o[0], o[1], acc0, acc1);
                apply9(wrow + 18, e[1], e[2], acc0, acc1);
                apply9(wrow + 27, o[1], o[2], acc0, acc1);
                apply9(wrow + 36, e[2], e[3], acc0, acc1);
            }
        }
#pragma unroll 1
        for (int j3 = 0; j3 < 3; j3++) {
            const float* inc = in0b + j3 * HW;
#pragma unroll 1
            for (int u = 0; u < 3; u++) {
                int r = h + u - 1;
                u64 e[4], o[3];
                load_row8_guard(inc + r * W, w0, (r >= 0 && r < H), colsafe, e, o);
                const float2* wrow = &s0[(j3 * 3 + u) * 27];
                apply9(wrow +  0, o[0], o[1], acc0, acc1);
                apply9(wrow +  9, e[1], e[2], acc0, acc1);
                apply9(wrow + 18, o[1], o[2], acc0, acc1);
            }
        }
    }

    // ---- epilogue: per-pixel dot with kernel, plus BN shift ----
    u64 r0 = 0ull, r1 = 0ull;
    const float* kp = ker + (size_t)b * 9 * HW + h * W + w0;
#pragma unroll
    for (int k = 0; k < 9; k++) {
        float4 kv = *(const float4*)(kp + k * HW);
        u64 sh2 = sS[k];
        fma2(r0, pk(kv.x, kv.y), add2(acc0[k], sh2));
        fma2(r1, pk(kv.z, kv.w), add2(acc1[k], sh2));
    }
    float o0, o1, o2, o3;
    upk(r0, o0, o1); upk(r1, o2, o3);

    // Interior writes only (ring owned by border part of kernel 1).
    if (h >= 1 && h <= H - 2) {
        float* op = out + (size_t)b * HW + h * W + w0;
        if (w0 == 0)          { op[1] = o1; op[2] = o2; op[3] = o3; }
        else if (w0 == W - 4) { op[0] = o0; op[1] = o1; op[2] = o2; }
        else                  { *(float4*)op = make_float4(o0, o1, o2, o3); }
    }
}

// ---------------------------------------------------------------------------
extern "C" void kernel_launch(void* const* d_in, const int* in_sizes, int n_in,
                              void* d_out, int out_size) {
    const float* ker = (const float*)d_in[0];
    const float* in  = (const float*)d_in[1];
    const float* in0 = (const float*)d_in[2];
    const float* cw  = (const float*)d_in[3];
    const float* gam = (const float*)d_in[4];
    const float* bet = (const float*)d_in[5];
    const float* mu  = (const float*)d_in[6];
    const float* var = (const float*)d_in[7];
    float* out = (float*)d_out;

    int bs = in_sizes[0] / (9 * HW);   // batch from kernel tensor size

    int ring_total = bs * (4 * W - 4);
    int nb = (ring_total + 127) / 128 + 1;   // +1 block for prep
    prep_border_kernel<<<nb, 128>>>(ker, in, in0, cw, gam, bet, mu, var, out, ring_total);

    dim3 blk(8, 16);
    dim3 grd(W / 32, H / 16, bs);
    cspn_main<<<grd, blk>>>(ker, in, in0, out);
}

// round 6
// speedup vs baseline: 1.3901x; 1.3901x over previous
#include <cuda_runtime.h>

#define H 512
#define W 512
#define HW (H * W)
#define BN_EPS 1e-5f

typedef unsigned long long u64;

// Precomputed effective weights (written by prep part of kernel 1).
__device__ float g_Weff[675];   // [(c*5+u)*5+v]*9+k : scaled 5x5 weights on input
__device__ float g_W0[243];     // [(j*3+u)*3+v]*9+k : scaled 3x3 weights on input0
__device__ float g_Shift[9];    // BN shift per k

// ---------------- packed f32x2 helpers ----------------
__device__ __forceinline__ u64 pk(float a, float b) {
    u64 d;
    asm("mov.b64 %0, {%1, %2};" : "=l"(d) : "f"(a), "f"(b));
    return d;
}
__device__ __forceinline__ void upk(u64 d, float& a, float& b) {
    asm("mov.b64 {%0, %1}, %2;" : "=f"(a), "=f"(b) : "l"(d));
}
__device__ __forceinline__ void fma2(u64& c, u64 a, u64 b) {
    asm("fma.rn.f32x2 %0, %1, %2, %0;" : "+l"(c) : "l"(a), "l"(b));
}
__device__ __forceinline__ u64 add2(u64 a, u64 b) {
    u64 d;
    asm("add.rn.f32x2 %0, %1, %2;" : "=l"(d) : "l"(a), "l"(b));
    return d;
}

// ---------------------------------------------------------------------------
// Kernel 1: last block = prep; other blocks = exact border ring.
// ---------------------------------------------------------------------------
__global__ void prep_border_kernel(const float* __restrict__ ker,
                                   const float* __restrict__ in,
                                   const float* __restrict__ in0,
                                   const float* __restrict__ cw,
                                   const float* __restrict__ gam,
                                   const float* __restrict__ bet,
                                   const float* __restrict__ mu,
                                   const float* __restrict__ var,
                                   float* __restrict__ out, int total) {
    if (blockIdx.x == gridDim.x - 1) {
        for (int tid = threadIdx.x; tid < 927; tid += blockDim.x) {
            if (tid < 675) {
                int k = tid % 9;
                int rest = tid / 9;
                int v = rest % 5; rest /= 5;
                int u = rest % 5;
                int c = rest / 5;
                float s = gam[k] * rsqrtf(var[k] + BN_EPS);
                float sum = 0.f;
                for (int ti = 0; ti < 3; ti++) {
                    int di = u - ti;
                    if (di < 0 || di > 2) continue;
                    for (int tj = 0; tj < 3; tj++) {
                        int dj = v - tj;
                        if (dj < 0 || dj > 2) continue;
                        int t = ti * 3 + tj;
                        if (c == 0 && t >= 4 && t <= 6) continue;
                        sum += cw[((k * 27 + c * 9 + t) * 3 + di) * 3 + dj];
                    }
                }
                g_Weff[tid] = s * sum;
            } else if (tid < 675 + 243) {
                int i = tid - 675;
                int k = i % 9;
                int rest = i / 9;
                int v = rest % 3; rest /= 3;
                int u = rest % 3;
                int j = rest / 3;
                float s = gam[k] * rsqrtf(var[k] + BN_EPS);
                g_W0[i] = s * cw[((k * 27 + 4 + j) * 3 + u) * 3 + v];
            } else {
                int k = tid - 918;
                float s = gam[k] * rsqrtf(var[k] + BN_EPS);
                g_Shift[k] = bet[k] - mu[k] * s;
            }
        }
        return;
    }

    // ---- border part: fully unrolled for MLP ----
    __shared__ float sw[2187];
    for (int i = threadIdx.x; i < 2187; i += blockDim.x) sw[i] = cw[i];
    __syncthreads();

    int gid = blockIdx.x * blockDim.x + threadIdx.x;
    if (gid >= total) return;

    const int RING = 4 * W - 4;  // 2044
    int b = gid / RING, pos = gid % RING;
    int h, w;
    if (pos < W)            { h = 0;       w = pos; }
    else if (pos < 2 * W)   { h = H - 1;   w = pos - W; }
    else {
        int p2 = pos - 2 * W;
        h = 1 + (p2 >> 1);
        w = (p2 & 1) ? (W - 1) : 0;
    }

    float acc[9];
#pragma unroll
    for (int k = 0; k < 9; k++) acc[k] = 0.f;

    const float* inb  = in  + (size_t)b * 3 * HW;
    const float* in0b = in0 + (size_t)b * 3 * HW;

#pragma unroll
    for (int dy = -1; dy <= 1; dy++) {
#pragma unroll
        for (int dx = -1; dx <= 1; dx++) {
            int qy = h + dy, qx = w + dx;
            bool qok = (qy >= 0 && qy < H && qx >= 0 && qx < W);
            int didx = (dy + 1) * 3 + (dx + 1);
#pragma unroll
            for (int ch = 0; ch < 27; ch++) {
                float val;
                if (ch >= 4 && ch <= 6) {
                    val = qok ? in0b[(ch - 4) * HW + qy * W + qx] : 0.f;
                } else {
                    int c = ch / 9, t = ch % 9;
                    int py = qy + t / 3 - 1, px = qx + t % 3 - 1;
                    bool pok = qok && (py >= 0 && py < H && px >= 0 && px < W);
                    val = pok ? inb[c * HW + py * W + px] : 0.f;
                }
#pragma unroll
                for (int k = 0; k < 9; k++)
                    acc[k] = fmaf(sw[(k * 27 + ch) * 9 + didx], val, acc[k]);
            }
        }
    }

    float r = 0.f;
#pragma unroll
    for (int k = 0; k < 9; k++) {
        float s  = gam[k] * rsqrtf(var[k] + BN_EPS);
        float sh = bet[k] - mu[k] * s;
        r = fmaf(ker[((size_t)b * 9 + k) * HW + h * W + w], fmaf(s, acc[k], sh), r);
    }
    out[(size_t)b * HW + h * W + w] = r;
}

// ---------------------------------------------------------------------------
// Row loaders: raw scalars v[8] + duplicated pairs dup[i] = {v[i],v[i]}
// over the 8-wide window [w0-2, w0+5].
// ---------------------------------------------------------------------------
__device__ __forceinline__ void load_row8_fast(const float* __restrict__ p,
                                               float v[8], u64 dup[8]) {
    u64 e0 = *(const u64*)(p - 2);
    u64 e1 = *(const u64*)(p);
    u64 e2 = *(const u64*)(p + 2);
    u64 e3 = *(const u64*)(p + 4);
    upk(e0, v[0], v[1]); upk(e1, v[2], v[3]);
    upk(e2, v[4], v[5]); upk(e3, v[6], v[7]);
#pragma unroll
    for (int i = 0; i < 8; i++) dup[i] = pk(v[i], v[i]);
}

__device__ __forceinline__ void load_row8_guard(const float* __restrict__ rowp, int w0,
                                                bool rowok, bool colsafe,
                                                float v[8], u64 dup[8]) {
    if (rowok && colsafe) {
        load_row8_fast(rowp + w0, v, dup);
        return;
    }
    if (rowok) {
#pragma unroll
        for (int i = 0; i < 8; i++) {
            int ww = w0 - 2 + i;
            v[i] = (ww >= 0 && ww < W) ? rowp[ww] : 0.f;
        }
    } else {
#pragma unroll
        for (int i = 0; i < 8; i++) v[i] = 0.f;
    }
#pragma unroll
    for (int i = 0; i < 8; i++) dup[i] = pk(v[i], v[i]);
}

// ---------------------------------------------------------------------------
// Apply one tap's 9 weights (natural pairs {w0,w1},{w2,w3},{w4,w5},{w6,w7},w8)
// to 4 pixels whose data starts at index `base` in v/dup.
// accp[p][j] holds packed accum for k={2j,2j+1} of pixel p; acc8[p] scalar k=8.
// ---------------------------------------------------------------------------
__device__ __forceinline__ void apply_tap(const float* __restrict__ wt,
                                          const float v[8], const u64 dup[8], int base,
                                          u64 accp[4][4], float acc8[4]) {
    ulonglong2 qa = *(const ulonglong2*)(wt);       // {w0,w1},{w2,w3}
    ulonglong2 qb = *(const ulonglong2*)(wt + 4);   // {w4,w5},{w6,w7}
    float w8 = wt[8];
#pragma unroll
    for (int p = 0; p < 4; p++) {
        u64 d = dup[base + p];
        fma2(accp[p][0], qa.x, d);
        fma2(accp[p][1], qa.y, d);
        fma2(accp[p][2], qb.x, d);
        fma2(accp[p][3], qb.y, d);
        acc8[p] = fmaf(w8, v[base + p], acc8[p]);
    }
}

// ---------------------------------------------------------------------------
// Kernel 2: main fused kernel. Block = 8x16 threads, thread -> 4 px along w.
// Weight SMEM layout: per tap 12 floats {w0..w8,pad,pad,pad}, 16B aligned.
// ---------------------------------------------------------------------------
__global__ __launch_bounds__(128) void cspn_main(const float* __restrict__ ker,
                                                 const float* __restrict__ in,
                                                 const float* __restrict__ in0,
                                                 float* __restrict__ out) {
    __shared__ __align__(16) float sW5[75 * 12];   // 3600 B
    __shared__ __align__(16) float s03[27 * 12];   // 1296 B
    __shared__ u64 sSp[4];                         // shift pairs {sh0,sh1}..{sh6,sh7}
    __shared__ float sS8;

    int tid = threadIdx.y * 8 + threadIdx.x;
    for (int i = tid; i < 75 * 12; i += 128) {
        int t5 = i / 12, k = i % 12;
        sW5[i] = (k < 9) ? g_Weff[t5 * 9 + k] : 0.f;
    }
    for (int i = tid; i < 27 * 12; i += 128) {
        int t3 = i / 12, k = i % 12;
        s03[i] = (k < 9) ? g_W0[t3 * 9 + k] : 0.f;
    }
    if (tid < 4) sSp[tid] = pk(g_Shift[2 * tid], g_Shift[2 * tid + 1]);
    if (tid == 4) sS8 = g_Shift[8];
    __syncthreads();

    const int b  = blockIdx.z;
    const int h  = blockIdx.y * 16 + threadIdx.y;
    const int w0 = blockIdx.x * 32 + threadIdx.x * 4;

    u64 accp[4][4];
    float acc8[4];
#pragma unroll
    for (int p = 0; p < 4; p++) {
        acc8[p] = 0.f;
#pragma unroll
        for (int j = 0; j < 4; j++) accp[p][j] = 0ull;
    }

    const float* inb  = in  + (size_t)b * 3 * HW;
    const float* in0b = in0 + (size_t)b * 3 * HW;

    const bool fast = (blockIdx.x >= 1) && (blockIdx.x <= (W / 32) - 2) &&
                      (blockIdx.y >= 1) && (blockIdx.y <= (H / 16) - 2);

    if (fast) {
        const float* base5 = inb + (h - 2) * W + w0;
#pragma unroll
        for (int c = 0; c < 3; c++) {
#pragma unroll
            for (int u = 0; u < 5; u++) {
                float v[8]; u64 dup[8];
                load_row8_fast(base5 + c * HW + u * W, v, dup);
                const float* wrow = &sW5[(c * 5 + u) * 60];
#pragma unroll
                for (int tv = 0; tv < 5; tv++)
                    apply_tap(wrow + tv * 12, v, dup, tv, accp, acc8);
            }
        }
        const float* base3 = in0b + (h - 1) * W + w0;
#pragma unroll
        for (int j3 = 0; j3 < 3; j3++) {
#pragma unroll
            for (int u = 0; u < 3; u++) {
                float v[8]; u64 dup[8];
                load_row8_fast(base3 + j3 * HW + u * W, v, dup);
                const float* wrow = &s03[(j3 * 3 + u) * 36];
#pragma unroll
                for (int tv = 0; tv < 3; tv++)
                    apply_tap(wrow + tv * 12, v, dup, 1 + tv, accp, acc8);
            }
        }
    } else {
        const bool colsafe = (w0 >= 2) && (w0 + 6 <= W);
#pragma unroll 1
        for (int c = 0; c < 3; c++) {
            const float* inc = inb + c * HW;
#pragma unroll 1
            for (int u = 0; u < 5; u++) {
                int r = h + u - 2;
                float v[8]; u64 dup[8];
                load_row8_guard(inc + r * W, w0, (r >= 0 && r < H), colsafe, v, dup);
                const float* wrow = &sW5[(c * 5 + u) * 60];
#pragma unroll
                for (int tv = 0; tv < 5; tv++)
                    apply_tap(wrow + tv * 12, v, dup, tv, accp, acc8);
            }
        }
#pragma unroll 1
        for (int j3 = 0; j3 < 3; j3++) {
            const float* inc = in0b + j3 * HW;
#pragma unroll 1
            for (int u = 0; u < 3; u++) {
                int r = h + u - 1;
                float v[8]; u64 dup[8];
                load_row8_guard(inc + r * W, w0, (r >= 0 && r < H), colsafe, v, dup);
                const float* wrow = &s03[(j3 * 3 + u) * 36];
#pragma unroll
                for (int tv = 0; tv < 3; tv++)
                    apply_tap(wrow + tv * 12, v, dup, 1 + tv, accp, acc8);
            }
        }
    }

    // ---- epilogue: per-pixel dot with kernel, plus BN shift ----
    const float* kp = ker + (size_t)b * 9 * HW + h * W + w0;
    float4 kv[9];
#pragma unroll
    for (int k = 0; k < 9; k++) kv[k] = *(const float4*)(kp + k * HW);

    u64 rp[4] = {0ull, 0ull, 0ull, 0ull};
#pragma unroll
    for (int j = 0; j < 4; j++) {
        u64 sh2 = sSp[j];
        const float4 ka = kv[2 * j];
        const float4 kb = kv[2 * j + 1];
        fma2(rp[0], pk(ka.x, kb.x), add2(accp[0][j], sh2));
        fma2(rp[1], pk(ka.y, kb.y), add2(accp[1][j], sh2));
        fma2(rp[2], pk(ka.z, kb.z), add2(accp[2][j], sh2));
        fma2(rp[3], pk(ka.w, kb.w), add2(accp[3][j], sh2));
    }
    float res[4];
    {
        const float4 k8 = kv[8];
        float sh8 = sS8;
        float lo, hi;
        upk(rp[0], lo, hi); res[0] = lo + hi + k8.x * (acc8[0] + sh8);
        upk(rp[1], lo, hi); res[1] = lo + hi + k8.y * (acc8[1] + sh8);
        upk(rp[2], lo, hi); res[2] = lo + hi + k8.z * (acc8[2] + sh8);
        upk(rp[3], lo, hi); res[3] = lo + hi + k8.w * (acc8[3] + sh8);
    }

    // Interior writes only (ring owned by border part of kernel 1).
    if (h >= 1 && h <= H - 2) {
        float* op = out + (size_t)b * HW + h * W + w0;
        if (w0 == 0)          { op[1] = res[1]; op[2] = res[2]; op[3] = res[3]; }
        else if (w0 == W - 4) { op[0] = res[0]; op[1] = res[1]; op[2] = res[2]; }
        else                  { *(float4*)op = make_float4(res[0], res[1], res[2], res[3]); }
    }
}

// ---------------------------------------------------------------------------
extern "C" void kernel_launch(void* const* d_in, const int* in_sizes, int n_in,
                              void* d_out, int out_size) {
    const float* ker = (const float*)d_in[0];
    const float* in  = (const float*)d_in[1];
    const float* in0 = (const float*)d_in[2];
    const float* cw  = (const float*)d_in[3];
    const float* gam = (const float*)d_in[4];
    const float* bet = (const float*)d_in[5];
    const float* mu  = (const float*)d_in[6];
    const float* var = (const float*)d_in[7];
    float* out = (float*)d_out;

    int bs = in_sizes[0] / (9 * HW);   // batch from kernel tensor size

    int ring_total = bs * (4 * W - 4);
    int nb = (ring_total + 127) / 128 + 1;   // +1 block for prep
    prep_border_kernel<<<nb, 128>>>(ker, in, in0, cw, gam, bet, mu, var, out, ring_total);

    dim3 blk(8, 16);
    dim3 grd(W / 32, H / 16, bs);
    cspn_main<<<grd, blk>>>(ker, in, in0, out);
}

// round 7
// speedup vs baseline: 1.6529x; 1.1891x over previous
#include <cuda_runtime.h>

#define H 512
#define W 512
#define HW (H * W)
#define BN_EPS 1e-5f

typedef unsigned long long u64;

// Precomputed effective weights (written by prep part of kernel 1).
__device__ float g_Weff[675];   // [(c*5+u)*5+v]*9+k : scaled 5x5 weights on input
__device__ float g_W0[243];     // [(j*3+u)*3+v]*9+k : scaled 3x3 weights on input0
__device__ float g_Shift[9];    // BN shift per k

// ---------------- packed f32x2 helpers ----------------
__device__ __forceinline__ u64 pk(float a, float b) {
    u64 d;
    asm("mov.b64 %0, {%1, %2};" : "=l"(d) : "f"(a), "f"(b));
    return d;
}
__device__ __forceinline__ void upk(u64 d, float& a, float& b) {
    asm("mov.b64 {%0, %1}, %2;" : "=f"(a), "=f"(b) : "l"(d));
}
__device__ __forceinline__ void fma2(u64& c, u64 a, u64 b) {
    asm("fma.rn.f32x2 %0, %1, %2, %0;" : "+l"(c) : "l"(a), "l"(b));
}
__device__ __forceinline__ u64 add2(u64 a, u64 b) {
    u64 d;
    asm("add.rn.f32x2 %0, %1, %2;" : "=l"(d) : "l"(a), "l"(b));
    return d;
}

// ---------------------------------------------------------------------------
// Kernel 1: last block = prep; other blocks = exact border ring with
// 9-way (didx) parallelism per pixel + smem reduction.
// Block = 144 threads = 16 pixels x 9 didx.
// ---------------------------------------------------------------------------
#define BPX 16
__global__ __launch_bounds__(144) void prep_border_kernel(
        const float* __restrict__ ker,
        const float* __restrict__ in,
        const float* __restrict__ in0,
        const float* __restrict__ cw,
        const float* __restrict__ gam,
        const float* __restrict__ bet,
        const float* __restrict__ mu,
        const float* __restrict__ var,
        float* __restrict__ out, int total) {
    if (blockIdx.x == gridDim.x - 1) {
        for (int tid = threadIdx.x; tid < 927; tid += blockDim.x) {
            if (tid < 675) {
                int k = tid % 9;
                int rest = tid / 9;
                int v = rest % 5; rest /= 5;
                int u = rest % 5;
                int c = rest / 5;
                float s = gam[k] * rsqrtf(var[k] + BN_EPS);
                float sum = 0.f;
                for (int ti = 0; ti < 3; ti++) {
                    int di = u - ti;
                    if (di < 0 || di > 2) continue;
                    for (int tj = 0; tj < 3; tj++) {
                        int dj = v - tj;
                        if (dj < 0 || dj > 2) continue;
                        int t = ti * 3 + tj;
                        if (c == 0 && t >= 4 && t <= 6) continue;
                        sum += cw[((k * 27 + c * 9 + t) * 3 + di) * 3 + dj];
                    }
                }
                g_Weff[tid] = s * sum;
            } else if (tid < 675 + 243) {
                int i = tid - 675;
                int k = i % 9;
                int rest = i / 9;
                int v = rest % 3; rest /= 3;
                int u = rest % 3;
                int j = rest / 3;
                float s = gam[k] * rsqrtf(var[k] + BN_EPS);
                g_W0[i] = s * cw[((k * 27 + 4 + j) * 3 + u) * 3 + v];
            } else {
                int k = tid - 918;
                float s = gam[k] * rsqrtf(var[k] + BN_EPS);
                g_Shift[k] = bet[k] - mu[k] * s;
            }
        }
        return;
    }

    __shared__ float sw[2187];
    __shared__ float pacc[BPX][9][9];   // [pixel][didx][k]
    for (int i = threadIdx.x; i < 2187; i += blockDim.x) sw[i] = cw[i];
    __syncthreads();

    const int px   = threadIdx.x / 9;                 // 0..15
    const int didx = threadIdx.x % 9;
    const int gpix = blockIdx.x * BPX + px;
    const bool active = (gpix < total);

    const int RING = 4 * W - 4;  // 2044
    int b = 0, h = 0, w = 0;
    if (active) {
        b = gpix / RING;
        int pos = gpix % RING;
        if (pos < W)            { h = 0;       w = pos; }
        else if (pos < 2 * W)   { h = H - 1;   w = pos - W; }
        else {
            int p2 = pos - 2 * W;
            h = 1 + (p2 >> 1);
            w = (p2 & 1) ? (W - 1) : 0;
        }
    }

    float acc[9];
#pragma unroll
    for (int k = 0; k < 9; k++) acc[k] = 0.f;

    if (active) {
        const float* inb  = in  + (size_t)b * 3 * HW;
        const float* in0b = in0 + (size_t)b * 3 * HW;
        const int dy = didx / 3 - 1, dx = didx % 3 - 1;
        const int qy = h + dy, qx = w + dx;
        const bool qok = (qy >= 0 && qy < H && qx >= 0 && qx < W);
#pragma unroll
        for (int ch = 0; ch < 27; ch++) {
            float val;
            if (ch >= 4 && ch <= 6) {
                val = qok ? in0b[(ch - 4) * HW + qy * W + qx] : 0.f;
            } else {
                int c = ch / 9, t = ch % 9;
                int py = qy + t / 3 - 1, px2 = qx + t % 3 - 1;
                bool pok = qok && (py >= 0 && py < H && px2 >= 0 && px2 < W);
                val = pok ? inb[c * HW + py * W + px2] : 0.f;
            }
#pragma unroll
            for (int k = 0; k < 9; k++)
                acc[k] = fmaf(sw[(k * 27 + ch) * 9 + didx], val, acc[k]);
        }
    }
#pragma unroll
    for (int k = 0; k < 9; k++) pacc[px][didx][k] = acc[k];
    __syncthreads();

    // one thread per pixel finishes
    if (threadIdx.x < BPX) {
        int p = threadIdx.x;
        int gp = blockIdx.x * BPX + p;
        if (gp < total) {
            int bb = gp / RING;
            int pos = gp % RING;
            int hh, ww;
            if (pos < W)            { hh = 0;       ww = pos; }
            else if (pos < 2 * W)   { hh = H - 1;   ww = pos - W; }
            else {
                int p2 = pos - 2 * W;
                hh = 1 + (p2 >> 1);
                ww = (p2 & 1) ? (W - 1) : 0;
            }
            float a[9];
#pragma unroll
            for (int k = 0; k < 9; k++) {
                float s = 0.f;
#pragma unroll
                for (int d = 0; d < 9; d++) s += pacc[p][d][k];
                a[k] = s;
            }
            float r = 0.f;
#pragma unroll
            for (int k = 0; k < 9; k++) {
                float sc = gam[k] * rsqrtf(var[k] + BN_EPS);
                float sh = bet[k] - mu[k] * sc;
                r = fmaf(ker[((size_t)bb * 9 + k) * HW + hh * W + ww],
                         fmaf(sc, a[k], sh), r);
            }
            out[(size_t)bb * HW + hh * W + ww] = r;
        }
    }
}

// ---------------------------------------------------------------------------
// Row loaders: raw scalars v[8] + duplicated pairs dup[i] = {v[i],v[i]}
// over the 8-wide window [w0-2, w0+5].
// ---------------------------------------------------------------------------
__device__ __forceinline__ void load_row8_fast(const float* __restrict__ p,
                                               float v[8], u64 dup[8]) {
    u64 e0 = *(const u64*)(p - 2);
    u64 e1 = *(const u64*)(p);
    u64 e2 = *(const u64*)(p + 2);
    u64 e3 = *(const u64*)(p + 4);
    upk(e0, v[0], v[1]); upk(e1, v[2], v[3]);
    upk(e2, v[4], v[5]); upk(e3, v[6], v[7]);
#pragma unroll
    for (int i = 0; i < 8; i++) dup[i] = pk(v[i], v[i]);
}

__device__ __forceinline__ void load_row8_guard(const float* __restrict__ rowp, int w0,
                                                bool rowok, bool colsafe,
                                                float v[8], u64 dup[8]) {
    if (rowok && colsafe) {
        load_row8_fast(rowp + w0, v, dup);
        return;
    }
    if (rowok) {
#pragma unroll
        for (int i = 0; i < 8; i++) {
            int ww = w0 - 2 + i;
            v[i] = (ww >= 0 && ww < W) ? rowp[ww] : 0.f;
        }
    } else {
#pragma unroll
        for (int i = 0; i < 8; i++) v[i] = 0.f;
    }
#pragma unroll
    for (int i = 0; i < 8; i++) dup[i] = pk(v[i], v[i]);
}

// ---------------------------------------------------------------------------
// Apply one tap's 9 weights (natural pairs) to 4 pixels starting at `base`.
// ---------------------------------------------------------------------------
__device__ __forceinline__ void apply_tap(const float* __restrict__ wt,
                                          const float v[8], const u64 dup[8], int base,
                                          u64 accp[4][4], float acc8[4]) {
    ulonglong2 qa = *(const ulonglong2*)(wt);       // {w0,w1},{w2,w3}
    ulonglong2 qb = *(const ulonglong2*)(wt + 4);   // {w4,w5},{w6,w7}
    float w8 = wt[8];
#pragma unroll
    for (int p = 0; p < 4; p++) {
        u64 d = dup[base + p];
        fma2(accp[p][0], qa.x, d);
        fma2(accp[p][1], qa.y, d);
        fma2(accp[p][2], qb.x, d);
        fma2(accp[p][3], qb.y, d);
        acc8[p] = fmaf(w8, v[base + p], acc8[p]);
    }
}

// ---------------------------------------------------------------------------
// Kernel 2: main fused kernel. Block = 8x16 threads, thread -> 4 px along w.
// ---------------------------------------------------------------------------
__global__ __launch_bounds__(128, 6) void cspn_main(const float* __restrict__ ker,
                                                    const float* __restrict__ in,
                                                    const float* __restrict__ in0,
                                                    float* __restrict__ out) {
    __shared__ __align__(16) float sW5[75 * 12];   // 3600 B
    __shared__ __align__(16) float s03[27 * 12];   // 1296 B
    __shared__ u64 sSp[4];
    __shared__ float sS8;

    int tid = threadIdx.y * 8 + threadIdx.x;
    for (int i = tid; i < 75 * 12; i += 128) {
        int t5 = i / 12, k = i % 12;
        sW5[i] = (k < 9) ? g_Weff[t5 * 9 + k] : 0.f;
    }
    for (int i = tid; i < 27 * 12; i += 128) {
        int t3 = i / 12, k = i % 12;
        s03[i] = (k < 9) ? g_W0[t3 * 9 + k] : 0.f;
    }
    if (tid < 4) sSp[tid] = pk(g_Shift[2 * tid], g_Shift[2 * tid + 1]);
    if (tid == 4) sS8 = g_Shift[8];
    __syncthreads();

    const int b  = blockIdx.z;
    const int h  = blockIdx.y * 16 + threadIdx.y;
    const int w0 = blockIdx.x * 32 + threadIdx.x * 4;

    u64 accp[4][4];
    float acc8[4];
#pragma unroll
    for (int p = 0; p < 4; p++) {
        acc8[p] = 0.f;
#pragma unroll
        for (int j = 0; j < 4; j++) accp[p][j] = 0ull;
    }

    const float* inb  = in  + (size_t)b * 3 * HW;
    const float* in0b = in0 + (size_t)b * 3 * HW;

    const bool fast = (blockIdx.x >= 1) && (blockIdx.x <= (W / 32) - 2) &&
                      (blockIdx.y >= 1) && (blockIdx.y <= (H / 16) - 2);

    if (fast) {
        const float* base5 = inb + (h - 2) * W + w0;
#pragma unroll
        for (int c = 0; c < 3; c++) {
#pragma unroll
            for (int u = 0; u < 5; u++) {
                float v[8]; u64 dup[8];
                load_row8_fast(base5 + c * HW + u * W, v, dup);
                const float* wrow = &sW5[(c * 5 + u) * 60];
#pragma unroll
                for (int tv = 0; tv < 5; tv++)
                    apply_tap(wrow + tv * 12, v, dup, tv, accp, acc8);
            }
        }
        const float* base3 = in0b + (h - 1) * W + w0;
#pragma unroll
        for (int j3 = 0; j3 < 3; j3++) {
#pragma unroll
            for (int u = 0; u < 3; u++) {
                float v[8]; u64 dup[8];
                load_row8_fast(base3 + j3 * HW + u * W, v, dup);
                const float* wrow = &s03[(j3 * 3 + u) * 36];
#pragma unroll
                for (int tv = 0; tv < 3; tv++)
                    apply_tap(wrow + tv * 12, v, dup, 1 + tv, accp, acc8);
            }
        }
    } else {
        const bool colsafe = (w0 >= 2) && (w0 + 6 <= W);
#pragma unroll 1
        for (int c = 0; c < 3; c++) {
            const float* inc = inb + c * HW;
#pragma unroll 1
            for (int u = 0; u < 5; u++) {
                int r = h + u - 2;
                float v[8]; u64 dup[8];
                load_row8_guard(inc + r * W, w0, (r >= 0 && r < H), colsafe, v, dup);
                const float* wrow = &sW5[(c * 5 + u) * 60];
#pragma unroll
                for (int tv = 0; tv < 5; tv++)
                    apply_tap(wrow + tv * 12, v, dup, tv, accp, acc8);
            }
        }
#pragma unroll 1
        for (int j3 = 0; j3 < 3; j3++) {
            const float* inc = in0b + j3 * HW;
#pragma unroll 1
            for (int u = 0; u < 3; u++) {
                int r = h + u - 1;
                float v[8]; u64 dup[8];
                load_row8_guard(inc + r * W, w0, (r >= 0 && r < H), colsafe, v, dup);
                const float* wrow = &s03[(j3 * 3 + u) * 36];
#pragma unroll
                for (int tv = 0; tv < 3; tv++)
                    apply_tap(wrow + tv * 12, v, dup, 1 + tv, accp, acc8);
            }
        }
    }

    // ---- epilogue: per-pixel dot with kernel (loaded pair-wise to keep
    //      register peak low), plus BN shift ----
    const float* kp = ker + (size_t)b * 9 * HW + h * W + w0;
    u64 rp[4] = {0ull, 0ull, 0ull, 0ull};
#pragma unroll
    for (int j = 0; j < 4; j++) {
        const float4 ka = *(const float4*)(kp + (2 * j) * HW);
        const float4 kb = *(const float4*)(kp + (2 * j + 1) * HW);
        u64 sh2 = sSp[j];
        fma2(rp[0], pk(ka.x, kb.x), add2(accp[0][j], sh2));
        fma2(rp[1], pk(ka.y, kb.y), add2(accp[1][j], sh2));
        fma2(rp[2], pk(ka.z, kb.z), add2(accp[2][j], sh2));
        fma2(rp[3], pk(ka.w, kb.w), add2(accp[3][j], sh2));
    }
    float res[4];
    {
        const float4 k8 = *(const float4*)(kp + 8 * HW);
        float sh8 = sS8;
        float lo, hi;
        upk(rp[0], lo, hi); res[0] = lo + hi + k8.x * (acc8[0] + sh8);
        upk(rp[1], lo, hi); res[1] = lo + hi + k8.y * (acc8[1] + sh8);
        upk(rp[2], lo, hi); res[2] = lo + hi + k8.z * (acc8[2] + sh8);
        upk(rp[3], lo, hi); res[3] = lo + hi + k8.w * (acc8[3] + sh8);
    }

    // Interior writes only (ring owned by border part of kernel 1).
    if (h >= 1 && h <= H - 2) {
        float* op = out + (size_t)b * HW + h * W + w0;
        if (w0 == 0)          { op[1] = res[1]; op[2] = res[2]; op[3] = res[3]; }
        else if (w0 == W - 4) { op[0] = res[0]; op[1] = res[1]; op[2] = res[2]; }
        else                  { *(float4*)op = make_float4(res[0], res[1], res[2], res[3]); }
    }
}

// ---------------------------------------------------------------------------
extern "C" void kernel_launch(void* const* d_in, const int* in_sizes, int n_in,
                              void* d_out, int out_size) {
    const float* ker = (const float*)d_in[0];
    const float* in  = (const float*)d_in[1];
    const float* in0 = (const float*)d_in[2];
    const float* cw  = (const float*)d_in[3];
    const float* gam = (const float*)d_in[4];
    const float* bet = (const float*)d_in[5];
    const float* mu  = (const float*)d_in[6];
    const float* var = (const float*)d_in[7];
    float* out = (float*)d_out;

    int bs = in_sizes[0] / (9 * HW);   // batch from kernel tensor size

    int ring_total = bs * (4 * W - 4);
    int nb = (ring_total + BPX - 1) / BPX + 1;   // +1 block for prep
    prep_border_kernel<<<nb, 144>>>(ker, in, in0, cw, gam, bet, mu, var, out, ring_total);

    dim3 blk(8, 16);
    dim3 grd(W / 32, H / 16, bs);
    cspn_main<<<grd, blk>>>(ker, in, in0, out);
}

// round 8
// speedup vs baseline: 1.7594x; 1.0644x over previous
#include <cuda_runtime.h>

#define H 512
#define W 512
#define HW (H * W)
#define BN_EPS 1e-5f
#define RING (4 * W - 4)          // 2044 ring pixels per batch
#define BPX 14                    // border pixels per border block (14*9=126 thr)

typedef unsigned long long u64;

// Precomputed effective weights (written by prep_kernel each launch).
__device__ float g_Weff[675];   // [(c*5+u)*5+v]*9+k
__device__ float g_W0[243];     // [(j*3+u)*3+v]*9+k
__device__ float g_Shift[9];

// ---------------- packed f32x2 helpers ----------------
__device__ __forceinline__ u64 pk(float a, float b) {
    u64 d;
    asm("mov.b64 %0, {%1, %2};" : "=l"(d) : "f"(a), "f"(b));
    return d;
}
__device__ __forceinline__ void upk(u64 d, float& a, float& b) {
    asm("mov.b64 {%0, %1}, %2;" : "=f"(a), "=f"(b) : "l"(d));
}
__device__ __forceinline__ void fma2(u64& c, u64 a, u64 b) {
    asm("fma.rn.f32x2 %0, %1, %2, %0;" : "+l"(c) : "l"(a), "l"(b));
}
__device__ __forceinline__ u64 add2(u64 a, u64 b) {
    u64 d;
    asm("add.rn.f32x2 %0, %1, %2;" : "=l"(d) : "l"(a), "l"(b));
    return d;
}

// ---------------------------------------------------------------------------
// Kernel 1: prep — one weight per thread (8 blocks x 128 threads >= 927).
// ---------------------------------------------------------------------------
__global__ void prep_kernel(const float* __restrict__ cw,
                            const float* __restrict__ gam,
                            const float* __restrict__ bet,
                            const float* __restrict__ mu,
                            const float* __restrict__ var) {
    int tid = blockIdx.x * blockDim.x + threadIdx.x;
    if (tid < 675) {
        int k = tid % 9;
        int rest = tid / 9;
        int v = rest % 5; rest /= 5;
        int u = rest % 5;
        int c = rest / 5;
        float s = gam[k] * rsqrtf(var[k] + BN_EPS);
        float sum = 0.f;
#pragma unroll
        for (int ti = 0; ti < 3; ti++) {
            int di = u - ti;
            if (di < 0 || di > 2) continue;
#pragma unroll
            for (int tj = 0; tj < 3; tj++) {
                int dj = v - tj;
                if (dj < 0 || dj > 2) continue;
                int t = ti * 3 + tj;
                if (c == 0 && t >= 4 && t <= 6) continue;   // replaced rows
                sum += cw[((k * 27 + c * 9 + t) * 3 + di) * 3 + dj];
            }
        }
        g_Weff[tid] = s * sum;
    } else if (tid < 675 + 243) {
        int i = tid - 675;
        int k = i % 9;
        int rest = i / 9;
        int v = rest % 3; rest /= 3;
        int u = rest % 3;
        int j = rest / 3;
        float s = gam[k] * rsqrtf(var[k] + BN_EPS);
        g_W0[i] = s * cw[((k * 27 + 4 + j) * 3 + u) * 3 + v];
    } else if (tid < 675 + 243 + 9) {
        int k = tid - 918;
        float s = gam[k] * rsqrtf(var[k] + BN_EPS);
        g_Shift[k] = bet[k] - mu[k] * s;
    }
}

// ---------------------------------------------------------------------------
// Row loader (fast): window [w0-2, w0+5] via LDG.64 + LDG.128 + LDG.64.
// ---------------------------------------------------------------------------
__device__ __forceinline__ void load_row8_fast(const float* __restrict__ p,
                                               float v[8], u64 dup[8]) {
    u64 a = *(const u64*)(p - 2);          // v0,v1
    float4 m = *(const float4*)(p);        // v2..v5 (16B aligned)
    u64 c = *(const u64*)(p + 4);          // v6,v7
    upk(a, v[0], v[1]);
    v[2] = m.x; v[3] = m.y; v[4] = m.z; v[5] = m.w;
    upk(c, v[6], v[7]);
#pragma unroll
    for (int i = 0; i < 8; i++) dup[i] = pk(v[i], v[i]);
}

__device__ __forceinline__ void load_row8_guard(const float* __restrict__ rowp, int w0,
                                                bool rowok, bool colsafe,
                                                float v[8], u64 dup[8]) {
    if (rowok && colsafe) {
        load_row8_fast(rowp + w0, v, dup);
        return;
    }
    if (rowok) {
#pragma unroll
        for (int i = 0; i < 8; i++) {
            int ww = w0 - 2 + i;
            v[i] = (ww >= 0 && ww < W) ? rowp[ww] : 0.f;
        }
    } else {
#pragma unroll
        for (int i = 0; i < 8; i++) v[i] = 0.f;
    }
#pragma unroll
    for (int i = 0; i < 8; i++) dup[i] = pk(v[i], v[i]);
}

// Apply one tap's 9 weights (pairs {w0,w1},{w2,w3},{w4,w5},{w6,w7}, w8 scalar).
__device__ __forceinline__ void apply_tap(const float* __restrict__ wt,
                                          const float v[8], const u64 dup[8], int base,
                                          u64 accp[4][4], float acc8[4]) {
    ulonglong2 qa = *(const ulonglong2*)(wt);
    ulonglong2 qb = *(const ulonglong2*)(wt + 4);
    float w8 = wt[8];
#pragma unroll
    for (int p = 0; p < 4; p++) {
        u64 d = dup[base + p];
        fma2(accp[p][0], qa.x, d);
        fma2(accp[p][1], qa.y, d);
        fma2(accp[p][2], qb.x, d);
        fma2(accp[p][3], qb.y, d);
        acc8[p] = fmaf(w8, v[base + p], acc8[p]);
    }
}

// ---------------------------------------------------------------------------
// Kernel 2: fused main + border.
//   blockIdx.y <  32 : main tile block (8x16 thr, 4 px/thread, 32x16 tile)
//   blockIdx.y >= 32 : border block (14 px x 9 didx) for the 1-px ring
// SMEM is a raw arena reused differently per block type.
// ---------------------------------------------------------------------------
#define NBY_EXTRA 10   // 16*10 = 160 border blocks per batch (need ceil(2044/14)=146)

__global__ __launch_bounds__(128, 6) void cspn_main(
        const float* __restrict__ ker,
        const float* __restrict__ in,
        const float* __restrict__ in0,
        const float* __restrict__ cw,
        const float* __restrict__ gam,
        const float* __restrict__ bet,
        const float* __restrict__ mu,
        const float* __restrict__ var,
        float* __restrict__ out) {
    __shared__ __align__(16) char smem_raw[13312];

    const int b = blockIdx.z;
    const int tid = threadIdx.y * 8 + threadIdx.x;

    if (blockIdx.y >= 32) {
        // ================= border path =================
        float* sw   = (float*)smem_raw;                 // [2187]
        float* pacc = (float*)(smem_raw + 8752);        // [BPX][9][9]

        for (int i = tid; i < 2187; i += 128) sw[i] = cw[i];
        __syncthreads();

        const int bidx = (blockIdx.y - 32) * 16 + blockIdx.x;   // 0..159
        const int base = bidx * BPX;

        const int px   = tid / 9;       // 0..13 (tid<126)
        const int didx = tid % 9;
        const int pos  = base + px;
        const bool active = (tid < 126) && (pos < RING);

        float acc[9];
#pragma unroll
        for (int k = 0; k < 9; k++) acc[k] = 0.f;

        if (active) {
            int h, w;
            if (pos < W)          { h = 0;     w = pos; }
            else if (pos < 2 * W) { h = H - 1; w = pos - W; }
            else {
                int p2 = pos - 2 * W;
                h = 1 + (p2 >> 1);
                w = (p2 & 1) ? (W - 1) : 0;
            }
            const float* inb  = in  + (size_t)b * 3 * HW;
            const float* in0b = in0 + (size_t)b * 3 * HW;
            const int dy = didx / 3 - 1, dx = didx % 3 - 1;
            const int qy = h + dy, qx = w + dx;
            const bool qok = (qy >= 0 && qy < H && qx >= 0 && qx < W);
#pragma unroll
            for (int ch = 0; ch < 27; ch++) {
                float val;
                if (ch >= 4 && ch <= 6) {
                    val = qok ? in0b[(ch - 4) * HW + qy * W + qx] : 0.f;
                } else {
                    int c = ch / 9, t = ch % 9;
                    int py = qy + t / 3 - 1, qx2 = qx + t % 3 - 1;
                    bool pok = qok && (py >= 0 && py < H && qx2 >= 0 && qx2 < W);
                    val = pok ? inb[c * HW + py * W + qx2] : 0.f;
                }
#pragma unroll
                for (int k = 0; k < 9; k++)
                    acc[k] = fmaf(sw[(k * 27 + ch) * 9 + didx], val, acc[k]);
            }
        }
        if (tid < 126) {
#pragma unroll
            for (int k = 0; k < 9; k++) pacc[(px * 9 + didx) * 9 + k] = acc[k];
        }
        __syncthreads();

        if (tid < BPX) {
            int pos2 = base + tid;
            if (pos2 < RING) {
                int hh, ww;
                if (pos2 < W)          { hh = 0;     ww = pos2; }
                else if (pos2 < 2 * W) { hh = H - 1; ww = pos2 - W; }
                else {
                    int p2 = pos2 - 2 * W;
                    hh = 1 + (p2 >> 1);
                    ww = (p2 & 1) ? (W - 1) : 0;
                }
                float r = 0.f;
#pragma unroll
                for (int k = 0; k < 9; k++) {
                    float s = 0.f;
#pragma unroll
                    for (int d = 0; d < 9; d++) s += pacc[(tid * 9 + d) * 9 + k];
                    float sc = gam[k] * rsqrtf(var[k] + BN_EPS);
                    float sh = bet[k] - mu[k] * sc;
                    r = fmaf(ker[((size_t)b * 9 + k) * HW + hh * W + ww],
                             fmaf(sc, s, sh), r);
                }
                out[(size_t)b * HW + hh * W + ww] = r;
            }
        }
        return;
    }

    // ================= main path =================
    float* sW5 = (float*)smem_raw;                   // [75*12]
    float* s03 = (float*)(smem_raw + 3600);          // [27*12]
    u64*  sSp  = (u64*)(smem_raw + 4896);            // [4]
    float* sS8 = (float*)(smem_raw + 4928);

    for (int i = tid; i < 75 * 12; i += 128) {
        int t5 = i / 12, k = i % 12;
        sW5[i] = (k < 9) ? g_Weff[t5 * 9 + k] : 0.f;
    }
    for (int i = tid; i < 27 * 12; i += 128) {
        int t3 = i / 12, k = i % 12;
        s03[i] = (k < 9) ? g_W0[t3 * 9 + k] : 0.f;
    }
    if (tid < 4) sSp[tid] = pk(g_Shift[2 * tid], g_Shift[2 * tid + 1]);
    if (tid == 4) *sS8 = g_Shift[8];
    __syncthreads();

    const int h  = blockIdx.y * 16 + threadIdx.y;
    const int w0 = blockIdx.x * 32 + threadIdx.x * 4;

    u64 accp[4][4];
    float acc8[4];
#pragma unroll
    for (int p = 0; p < 4; p++) {
        acc8[p] = 0.f;
#pragma unroll
        for (int j = 0; j < 4; j++) accp[p][j] = 0ull;
    }

    const float* inb  = in  + (size_t)b * 3 * HW;
    const float* in0b = in0 + (size_t)b * 3 * HW;

    const bool fast = (blockIdx.x >= 1) && (blockIdx.x <= (W / 32) - 2) &&
                      (blockIdx.y >= 1) && (blockIdx.y <= 30);

    if (fast) {
        const float* base5 = inb + (h - 2) * W + w0;
#pragma unroll
        for (int c = 0; c < 3; c++) {
#pragma unroll
            for (int u = 0; u < 5; u++) {
                float v[8]; u64 dup[8];
                load_row8_fast(base5 + c * HW + u * W, v, dup);
                const float* wrow = &sW5[(c * 5 + u) * 60];
#pragma unroll
                for (int tv = 0; tv < 5; tv++)
                    apply_tap(wrow + tv * 12, v, dup, tv, accp, acc8);
            }
        }
        const float* base3 = in0b + (h - 1) * W + w0;
#pragma unroll
        for (int j3 = 0; j3 < 3; j3++) {
#pragma unroll
            for (int u = 0; u < 3; u++) {
                float v[8]; u64 dup[8];
                load_row8_fast(base3 + j3 * HW + u * W, v, dup);
                const float* wrow = &s03[(j3 * 3 + u) * 36];
#pragma unroll
                for (int tv = 0; tv < 3; tv++)
                    apply_tap(wrow + tv * 12, v, dup, 1 + tv, accp, acc8);
            }
        }
    } else {
        const bool colsafe = (w0 >= 2) && (w0 + 6 <= W);
#pragma unroll 1
        for (int c = 0; c < 3; c++) {
            const float* inc = inb + c * HW;
#pragma unroll 1
            for (int u = 0; u < 5; u++) {
                int r = h + u - 2;
                float v[8]; u64 dup[8];
                load_row8_guard(inc + r * W, w0, (r >= 0 && r < H), colsafe, v, dup);
                const float* wrow = &sW5[(c * 5 + u) * 60];
#pragma unroll
                for (int tv = 0; tv < 5; tv++)
                    apply_tap(wrow + tv * 12, v, dup, tv, accp, acc8);
            }
        }
#pragma unroll 1
        for (int j3 = 0; j3 < 3; j3++) {
            const float* inc = in0b + j3 * HW;
#pragma unroll 1
            for (int u = 0; u < 3; u++) {
                int r = h + u - 1;
                float v[8]; u64 dup[8];
                load_row8_guard(inc + r * W, w0, (r >= 0 && r < H), colsafe, v, dup);
                const float* wrow = &s03[(j3 * 3 + u) * 36];
#pragma unroll
                for (int tv = 0; tv < 3; tv++)
                    apply_tap(wrow + tv * 12, v, dup, 1 + tv, accp, acc8);
            }
        }
    }

    // ---- epilogue ----
    const float* kp = ker + (size_t)b * 9 * HW + h * W + w0;
    u64 rp[4] = {0ull, 0ull, 0ull, 0ull};
#pragma unroll
    for (int j = 0; j < 4; j++) {
        const float4 ka = *(const float4*)(kp + (2 * j) * HW);
        const float4 kb = *(const float4*)(kp + (2 * j + 1) * HW);
        u64 sh2 = sSp[j];
        fma2(rp[0], pk(ka.x, kb.x), add2(accp[0][j], sh2));
        fma2(rp[1], pk(ka.y, kb.y), add2(accp[1][j], sh2));
        fma2(rp[2], pk(ka.z, kb.z), add2(accp[2][j], sh2));
        fma2(rp[3], pk(ka.w, kb.w), add2(accp[3][j], sh2));
    }
    float res[4];
    {
        const float4 k8 = *(const float4*)(kp + 8 * HW);
        float sh8 = *sS8;
        float lo, hi;
        upk(rp[0], lo, hi); res[0] = lo + hi + k8.x * (acc8[0] + sh8);
        upk(rp[1], lo, hi); res[1] = lo + hi + k8.y * (acc8[1] + sh8);
        upk(rp[2], lo, hi); res[2] = lo + hi + k8.z * (acc8[2] + sh8);
        upk(rp[3], lo, hi); res[3] = lo + hi + k8.w * (acc8[3] + sh8);
    }

    // Interior writes only (ring owned by border blocks).
    if (h >= 1 && h <= H - 2) {
        float* op = out + (size_t)b * HW + h * W + w0;
        if (w0 == 0)          { op[1] = res[1]; op[2] = res[2]; op[3] = res[3]; }
        else if (w0 == W - 4) { op[0] = res[0]; op[1] = res[1]; op[2] = res[2]; }
        else                  { *(float4*)op = make_float4(res[0], res[1], res[2], res[3]); }
    }
}

// ---------------------------------------------------------------------------
extern "C" void kernel_launch(void* const* d_in, const int* in_sizes, int n_in,
                              void* d_out, int out_size) {
    const float* ker = (const float*)d_in[0];
    const float* in  = (const float*)d_in[1];
    const float* in0 = (const float*)d_in[2];
    const float* cw  = (const float*)d_in[3];
    const float* gam = (const float*)d_in[4];
    const float* bet = (const float*)d_in[5];
    const float* mu  = (const float*)d_in[6];
    const float* var = (const float*)d_in[7];
    float* out = (float*)d_out;

    int bs = in_sizes[0] / (9 * HW);   // batch from kernel tensor size

    prep_kernel<<<8, 128>>>(cw, gam, bet, mu, var);

    dim3 blk(8, 16);
    dim3 grd(W / 32, 32 + NBY_EXTRA, bs);
    cspn_main<<<grd, blk>>>(ker, in, in0, cw, gam, bet, mu, var, out);
}